// round 2
// baseline (speedup 1.0000x reference)
#include <cuda_runtime.h>
#include <cuda_bf16.h>

// ---------------- problem constants ----------------
constexpr int Bb   = 8;
constexpr int Ss   = 8192;
constexpr int Nn   = Bb * Ss;      // 65536 tokens
constexpr int Dd   = 512;
constexpr int Hh   = 8;
constexpr int HK   = 2;
constexpr int Gg   = Hh / HK;      // 4
constexpr int DH   = 64;
constexpr int Mm   = 64;
constexpr int DFF  = 2048;
constexpr int NCLS = 2;

// ---------------- scratch (device globals; no mallocs allowed) ----------------
__device__ float g_x [(long)Nn * Dd];        // 128 MB  (residual stream)
__device__ float g_h [(long)Nn * Dd];        // 128 MB  (rmsnorm out, reused)
__device__ float g_q [(long)Nn * Hh * DH];   // 128 MB  (q; reused as attn out)
__device__ float g_k [(long)Nn * HK * DH];   // 32 MB
__device__ float g_v [(long)Nn * HK * DH];   // 32 MB
__device__ float g_pq[(long)Nn * Hh * Mm];   // 128 MB
__device__ float g_pk[(long)Nn * HK * Mm];   // 32 MB
__device__ float g_ff[(long)Nn * DFF];       // 512 MB
__device__ float g_kv[Bb * HK * Mm * DH];    // 256 KB
__device__ float g_z [Bb * HK * Mm];
__device__ float g_xm[Bb * Dd];

// ---------------- f32x2 packed helpers (B300 FFMA2 path) ----------------
typedef unsigned long long ull;

__device__ __forceinline__ ull pack2(float x) {
    ull r; unsigned u = __float_as_uint(x);
    asm("mov.b64 %0, {%1, %1};" : "=l"(r) : "r"(u));
    return r;
}
__device__ __forceinline__ ull fma2(ull a, ull b, ull c) {
    ull d;
    asm("fma.rn.f32x2 %0, %1, %2, %3;" : "=l"(d) : "l"(a), "l"(b), "l"(c));
    return d;
}
__device__ __forceinline__ float2 unpack2(ull v) {
    unsigned lo, hi;
    asm("mov.b64 {%0, %1}, %2;" : "=r"(lo), "=r"(hi) : "l"(v));
    return make_float2(__uint_as_float(lo), __uint_as_float(hi));
}

// ---------------- generic tiled SGEMM ----------------
// C[M,N] = act( A[M,K] @ B0[K,N] (,B1) ) (+ X residual)
// BM=128, BK=16, 256 threads, per-thread 8 rows x TN cols via f32x2 row pairs.
// ACT: 0 = none, 1 = exp(-|x|). DUAL: C = silu(g)*u with g from B0, u from B1.
template<int BN, int TN, int ACT, bool DUAL, bool RESID>
__global__ __launch_bounds__(256)
void gemm_k(const float* __restrict__ A, const float* __restrict__ B0,
            const float* __restrict__ B1, const float* __restrict__ X,
            float* __restrict__ C, int Md, int Nd, int Kd)
{
    constexpr int BM = 128, BK = 16;
    __shared__ float As[BK][BM + 4];
    __shared__ float Bs0[BK][BN];
    __shared__ float Bs1[DUAL ? BK : 1][BN];

    const int t  = threadIdx.x;
    const int tx = t & 15;         // 16 col groups
    const int ty = t >> 4;         // 16 row groups (8 rows each)
    const long row0 = (long)blockIdx.y * BM;
    const long col0 = (long)blockIdx.x * BN;

    ull acc0[4][TN];
    ull acc1[DUAL ? 4 : 1][TN];
    #pragma unroll
    for (int i = 0; i < 4; i++)
        #pragma unroll
        for (int j = 0; j < TN; j++) { acc0[i][j] = 0ull; if (DUAL) acc1[i][j] = 0ull; }

    for (int k0 = 0; k0 < Kd; k0 += BK) {
        // --- load A tile (transposed into smem) ---
        #pragma unroll
        for (int l = 0; l < 2; l++) {
            int lin = t + l * 256;
            int ar = lin >> 2, ac = (lin & 3) * 4;
            float4 va = *(const float4*)(A + (row0 + ar) * Kd + k0 + ac);
            As[ac + 0][ar] = va.x; As[ac + 1][ar] = va.y;
            As[ac + 2][ar] = va.z; As[ac + 3][ar] = va.w;
        }
        // --- load B tile(s) ---
        if (BN == 128) {
            #pragma unroll
            for (int l = 0; l < 2; l++) {
                int lin = t + l * 256;
                int br = lin >> 5, bc = (lin & 31) * 4;
                *(float4*)&Bs0[br][bc] = *(const float4*)(B0 + (long)(k0 + br) * Nd + col0 + bc);
            }
        } else { // BN == 64
            int br = t >> 4, bc = (t & 15) * 4;
            *(float4*)&Bs0[br][bc] = *(const float4*)(B0 + (long)(k0 + br) * Nd + col0 + bc);
            if (DUAL)
                *(float4*)&Bs1[br][bc] = *(const float4*)(B1 + (long)(k0 + br) * Nd + col0 + bc);
        }
        __syncthreads();

        #pragma unroll
        for (int kk = 0; kk < BK; kk++) {
            // 8 A rows for this thread as 4 packed row-pairs
            float4 a0 = *(const float4*)&As[kk][ty * 8];
            float4 a1 = *(const float4*)&As[kk][ty * 8 + 4];
            ull av[4];
            { float2 p; p.x = a0.x; p.y = a0.y; av[0] = *(ull*)&p; }
            { float2 p; p.x = a0.z; p.y = a0.w; av[1] = *(ull*)&p; }
            { float2 p; p.x = a1.x; p.y = a1.y; av[2] = *(ull*)&p; }
            { float2 p; p.x = a1.z; p.y = a1.w; av[3] = *(ull*)&p; }

            float bv0[TN];
            if (TN == 8) {
                float4 b0a = *(const float4*)&Bs0[kk][tx * TN];
                float4 b0b = *(const float4*)&Bs0[kk][tx * TN + 4];
                bv0[0]=b0a.x; bv0[1]=b0a.y; bv0[2]=b0a.z; bv0[3]=b0a.w;
                bv0[4]=b0b.x; bv0[5]=b0b.y; bv0[6]=b0b.z; bv0[7]=b0b.w;
            } else {
                float4 b0a = *(const float4*)&Bs0[kk][tx * TN];
                bv0[0]=b0a.x; bv0[1]=b0a.y; bv0[2]=b0a.z; bv0[3]=b0a.w;
            }
            #pragma unroll
            for (int j = 0; j < TN; j++) {
                ull bb = pack2(bv0[j]);
                #pragma unroll
                for (int i = 0; i < 4; i++) acc0[i][j] = fma2(av[i], bb, acc0[i][j]);
            }
            if (DUAL) {
                float4 b1a = *(const float4*)&Bs1[kk][tx * TN];
                float bv1[4] = { b1a.x, b1a.y, b1a.z, b1a.w };
                #pragma unroll
                for (int j = 0; j < TN; j++) {
                    ull bb = pack2(bv1[j]);
                    #pragma unroll
                    for (int i = 0; i < 4; i++) acc1[i][j] = fma2(av[i], bb, acc1[i][j]);
                }
            }
        }
        __syncthreads();
    }

    // --- epilogue ---
    #pragma unroll
    for (int i2 = 0; i2 < 4; i2++) {
        long r0 = row0 + ty * 8 + i2 * 2;
        #pragma unroll
        for (int j = 0; j < TN; j++) {
            long c = col0 + tx * TN + j;
            float2 v = unpack2(acc0[i2][j]);
            float val0 = v.x, val1 = v.y;
            if (DUAL) {
                float2 u = unpack2(acc1[i2][j]);
                val0 = val0 / (1.f + expf(-val0)) * u.x;
                val1 = val1 / (1.f + expf(-val1)) * u.y;
            }
            if (ACT == 1) { val0 = expf(-fabsf(val0)); val1 = expf(-fabsf(val1)); }
            if (RESID)    { val0 += X[r0 * Nd + c];    val1 += X[(r0 + 1) * Nd + c]; }
            C[r0 * Nd + c]       = val0;
            C[(r0 + 1) * Nd + c] = val1;
        }
    }
}

// ---------------- embedding gather ----------------
__global__ void embed_k(const int* __restrict__ ids, const float* __restrict__ emb,
                        float* __restrict__ x) {
    long n = blockIdx.x;
    int  t = threadIdx.x;  // 128 threads, float4 each (D=512)
    ((float4*)x)[n * 128 + t] = ((const float4*)emb)[(long)ids[n] * 128 + t];
}

// ---------------- rmsnorm ----------------
__global__ void rmsnorm_k(const float* __restrict__ x, const float* __restrict__ g,
                          float* __restrict__ o) {
    long n = blockIdx.x;
    int  t = threadIdx.x;  // 128
    float4 v = ((const float4*)(x + n * Dd))[t];
    float ss = v.x * v.x + v.y * v.y + v.z * v.z + v.w * v.w;
    #pragma unroll
    for (int o2 = 16; o2; o2 >>= 1) ss += __shfl_xor_sync(0xffffffffu, ss, o2);
    __shared__ float sm[4];
    if ((t & 31) == 0) sm[t >> 5] = ss;
    __syncthreads();
    float tot = sm[0] + sm[1] + sm[2] + sm[3];
    float sc = rsqrtf(tot * (1.f / 512.f) + 1e-6f);
    float4 gg = ((const float4*)g)[t];
    float4 r;
    r.x = v.x * sc * gg.x; r.y = v.y * sc * gg.y;
    r.z = v.z * sc * gg.z; r.w = v.w * sc * gg.w;
    ((float4*)(o + n * Dd))[t] = r;
}

// ---------------- zero scratch accumulators ----------------
__global__ void zero_k() {
    int i = blockIdx.x * blockDim.x + threadIdx.x;
    if (i < Bb * HK * Mm * DH) g_kv[i] = 0.f;
    if (i < Bb * HK * Mm)      g_z[i]  = 0.f;
    if (i < Bb * Dd)           g_xm[i] = 0.f;
}

// ---------------- kv state + normalizer: kv[b,hk] = pk^T @ v ; z = sum pk ----------------
__global__ __launch_bounds__(256) void kvz_k(const float* __restrict__ pk,
                                             const float* __restrict__ v) {
    int bk = blockIdx.x;            // b*HK + hk
    int b  = bk / HK, hk = bk % HK;
    int s0 = blockIdx.y * 256;      // 32 chunks of 256 tokens
    __shared__ float spk[8][64], sv[8][64];
    int t  = threadIdx.x;
    int mB = (t & 15) * 4, dB = (t >> 4) * 4;
    float acc[4][4] = {};
    float zacc = 0.f;

    for (int st = 0; st < 32; st++) {
        int sbase = s0 + st * 8;
        {
            int half = t >> 7, tt = t & 127;
            int sl = tt >> 4, c = (tt & 15) * 4;
            long row = ((long)(b * Ss + sbase + sl) * HK + hk) * 64;
            const float* src = half ? v : pk;
            float4 val = *(const float4*)(src + row + c);
            float* dst = half ? &sv[sl][c] : &spk[sl][c];
            *(float4*)dst = val;
        }
        __syncthreads();
        #pragma unroll
        for (int ssi = 0; ssi < 8; ssi++) {
            float pm[4], vv[4];
            #pragma unroll
            for (int i = 0; i < 4; i++) { pm[i] = spk[ssi][mB + i]; vv[i] = sv[ssi][dB + i]; }
            #pragma unroll
            for (int i = 0; i < 4; i++)
                #pragma unroll
                for (int j = 0; j < 4; j++) acc[i][j] += pm[i] * vv[j];
            if (t < 64) zacc += spk[ssi][t];
        }
        __syncthreads();
    }
    long base = (long)bk * 64 * 64;
    #pragma unroll
    for (int i = 0; i < 4; i++)
        #pragma unroll
        for (int j = 0; j < 4; j++)
            atomicAdd(&g_kv[base + (mB + i) * 64 + dB + j], acc[i][j]);
    if (t < 64) atomicAdd(&g_z[bk * 64 + t], zacc);
}

// ---------------- attention combine: attn = (pq @ kv) / (pq @ z + eps) ----------------
__global__ __launch_bounds__(256) void attn_k(const float* __restrict__ pq,
                                              float* __restrict__ attn) {
    int bk = blockIdx.x;            // b*HK + hk
    int b  = bk / HK, hk = bk % HK;
    int sTile = blockIdx.y * 64;
    __shared__ float kvs[64][64];
    __shared__ float zs[64];
    int t = threadIdx.x;
    {
        float* kf = &kvs[0][0];
        const float4* src = (const float4*)(g_kv + (long)bk * 4096);
        #pragma unroll
        for (int l = 0; l < 4; l++) ((float4*)kf)[t + l * 256] = src[t + l * 256];
        if (t < 16) ((float4*)zs)[t] = ((const float4*)(g_z + bk * 64))[t];
    }
    __syncthreads();
    int w = t >> 5, lane = t & 31;
    for (int it = 0; it < 32; it++) {
        int pi = w * 32 + it;
        int sl = pi >> 2, g = pi & 3;
        long n = (long)b * Ss + sTile + sl;
        const float* pqp = pq + (n * Hh + hk * Gg + g) * 64;
        float a0 = 0.f, a1 = 0.f, den = 0.f;
        #pragma unroll 8
        for (int m = 0; m < 64; m++) {
            float pm = pqp[m];
            a0  += pm * kvs[m][lane];
            a1  += pm * kvs[m][lane + 32];
            den += pm * zs[m];
        }
        float r = 1.f / (den + 1e-6f);
        float* op = attn + n * 512 + (hk * Gg + g) * 64;
        op[lane]      = a0 * r;
        op[lane + 32] = a1 * r;
    }
}

// ---------------- mean pool (sum; divide at head) ----------------
__global__ void pool_k(const float* __restrict__ x) {
    int b = blockIdx.x, chunk = blockIdx.y;   // 32 chunks of 256 tokens
    int t = threadIdx.x;                      // 256 threads x 2 floats
    float2 acc = make_float2(0.f, 0.f);
    const float* base = x + ((long)b * Ss + chunk * 256) * Dd + t * 2;
    #pragma unroll 4
    for (int s = 0; s < 256; s++) {
        float2 v = *(const float2*)(base + (long)s * Dd);
        acc.x += v.x; acc.y += v.y;
    }
    atomicAdd(&g_xm[b * Dd + t * 2],     acc.x);
    atomicAdd(&g_xm[b * Dd + t * 2 + 1], acc.y);
}

// ---------------- classifier head ----------------
__global__ void head_k(const float* __restrict__ Wc, const float* __restrict__ bc,
                       float* __restrict__ out) {
    int w = threadIdx.x >> 5, lane = threadIdx.x & 31;
    for (int p = w; p < Bb * NCLS; p += 8) {
        int b = p >> 1, c = p & 1;
        float s = 0.f;
        for (int d = lane; d < Dd; d += 32) s += g_xm[b * Dd + d] * Wc[d * NCLS + c];
        #pragma unroll
        for (int o = 16; o; o >>= 1) s += __shfl_xor_sync(0xffffffffu, s, o);
        if (lane == 0) out[p] = s * (1.f / (float)Ss) + bc[c];
    }
}

// ---------------- launch ----------------
extern "C" void kernel_launch(void* const* d_in, const int* in_sizes, int n_in,
                              void* d_out, int out_size) {
    const int*   ids  = (const int*)  d_in[0];
    const float* emb  = (const float*)d_in[1];
    const float* Wq   = (const float*)d_in[2];
    const float* Wk   = (const float*)d_in[3];
    const float* Wv   = (const float*)d_in[4];
    const float* Wphi = (const float*)d_in[5];
    const float* Wo   = (const float*)d_in[6];
    const float* g1   = (const float*)d_in[7];
    const float* g2   = (const float*)d_in[8];
    const float* Wg   = (const float*)d_in[9];
    const float* Wu   = (const float*)d_in[10];
    const float* Wd   = (const float*)d_in[11];
    const float* Wc   = (const float*)d_in[12];
    const float* bc   = (const float*)d_in[13];
    float* out = (float*)d_out;

    float* x  = g_x;  float* h = g_h;  float* q = g_q;
    float* k  = g_k;  float* v = g_v;
    float* pq = g_pq; float* pk = g_pk; float* ff = g_ff;
    float* attn = g_q;  // reuse: q dead after phi

    zero_k<<<256, 256>>>();
    embed_k  <<<Nn, 128>>>(ids, emb, x);
    rmsnorm_k<<<Nn, 128>>>(x, g1, h);

    // projections
    gemm_k<128, 8, 0, false, false><<<dim3(Dd / 128, Nn / 128), 256>>>(h, Wq, nullptr, nullptr, q, Nn, Dd, Dd);
    gemm_k<128, 8, 0, false, false><<<dim3(1,        Nn / 128), 256>>>(h, Wk, nullptr, nullptr, k, Nn, HK * DH, Dd);
    gemm_k<128, 8, 0, false, false><<<dim3(1,        Nn / 128), 256>>>(h, Wv, nullptr, nullptr, v, Nn, HK * DH, Dd);

    // Laplacian feature maps: rows are contiguous per-(token,head) 64-vectors
    gemm_k<64, 4, 1, false, false><<<dim3(1, (Nn * Hh) / 128), 256>>>(q, Wphi, nullptr, nullptr, pq, Nn * Hh, Mm, DH);
    gemm_k<64, 4, 1, false, false><<<dim3(1, (Nn * HK) / 128), 256>>>(k, Wphi, nullptr, nullptr, pk, Nn * HK, Mm, DH);

    // global kv state + normalizer, then combine
    kvz_k <<<dim3(Bb * HK, 32),  256>>>(pk, v);
    attn_k<<<dim3(Bb * HK, Ss / 64), 256>>>(pq, attn);

    // output projection + residual
    gemm_k<128, 8, 0, false, true><<<dim3(Dd / 128, Nn / 128), 256>>>(attn, Wo, nullptr, x, x, Nn, Dd, Dd);

    // FFN
    rmsnorm_k<<<Nn, 128>>>(x, g2, h);
    gemm_k<64, 4, 0, true,  false><<<dim3(DFF / 64, Nn / 128), 256>>>(h, Wg, Wu, nullptr, ff, Nn, DFF, Dd);
    gemm_k<128, 8, 0, false, true><<<dim3(Dd / 128, Nn / 128), 256>>>(ff, Wd, nullptr, x, x, Nn, Dd, DFF);

    // pool + head
    pool_k<<<dim3(Bb, 32), 256>>>(x);
    head_k<<<1, 256>>>(Wc, bc, out);
}

// round 4
// speedup vs baseline: 9.5355x; 9.5355x over previous
#include <cuda_runtime.h>
#include <cuda_bf16.h>

// ---------------- problem constants ----------------
constexpr int Bb   = 8;
constexpr int Ss   = 8192;
constexpr int Nn   = Bb * Ss;      // 65536 tokens
constexpr int Dd   = 512;
constexpr int Hh   = 8;
constexpr int HK   = 2;
constexpr int Gg   = Hh / HK;      // 4
constexpr int DH   = 64;
constexpr int Mm   = 64;
constexpr int DFF  = 2048;
constexpr int NCLS = 2;

// ---------------- scratch (device globals; no mallocs allowed) ----------------
__device__ float g_x [(long)Nn * Dd];        // residual stream
__device__ float g_h [(long)Nn * Dd];        // rmsnorm out (tf32-rounded)
__device__ float g_q [(long)Nn * Hh * DH];   // q (tf32-rounded); reused as attn out
__device__ float g_k [(long)Nn * HK * DH];   // k (tf32-rounded)
__device__ float g_v [(long)Nn * HK * DH];
__device__ float g_pq[(long)Nn * Hh * Mm];
__device__ float g_pk[(long)Nn * HK * Mm];
__device__ float g_ff[(long)Nn * DFF];       // gate out, then silu*u (tf32)
__device__ float g_u2[(long)Nn * DFF];       // up out
__device__ float g_kv[Bb * HK * Mm * DH];
__device__ float g_z [Bb * HK * Mm];
__device__ float g_xm[Bb * Dd];
// tf32-rounded weights
__device__ float g_wq [Dd * Hh * DH];
__device__ float g_wk [Dd * HK * DH];
__device__ float g_wv [Dd * HK * DH];
__device__ float g_wphi[DH * Mm];
__device__ float g_wo [Hh * DH * Dd];
__device__ float g_wg [Dd * DFF];
__device__ float g_wu [Dd * DFF];
__device__ float g_wd [DFF * Dd];

// ---------------- helpers ----------------
__device__ __forceinline__ float to_tf32(float x) {
    float r; asm("cvt.rna.tf32.f32 %0, %1;" : "=f"(r) : "f"(x)); return r;
}
__device__ __forceinline__ void cpa16(float* s, const float* g) {
    unsigned a = (unsigned)__cvta_generic_to_shared(s);
    asm volatile("cp.async.ca.shared.global [%0], [%1], 16;" :: "r"(a), "l"(g));
}
__device__ __forceinline__ void cpa8(float* s, const float* g) {
    unsigned a = (unsigned)__cvta_generic_to_shared(s);
    asm volatile("cp.async.ca.shared.global [%0], [%1], 8;" :: "r"(a), "l"(g));
}
__device__ __forceinline__ void cp_commit() {
    asm volatile("cp.async.commit_group;" ::: "memory");
}
template<int N> __device__ __forceinline__ void cp_wait() {
    asm volatile("cp.async.wait_group %0;" :: "n"(N) : "memory");
}
__device__ __forceinline__ void mma_tf32(float& d0, float& d1, float& d2, float& d3,
                                         unsigned a0, unsigned a1, unsigned a2, unsigned a3,
                                         unsigned b0, unsigned b1) {
    asm volatile("mma.sync.aligned.m16n8k8.row.col.f32.tf32.tf32.f32 "
                 "{%0,%1,%2,%3}, {%4,%5,%6,%7}, {%8,%9}, {%0,%1,%2,%3};"
                 : "+f"(d0), "+f"(d1), "+f"(d2), "+f"(d3)
                 : "r"(a0), "r"(a1), "r"(a2), "r"(a3), "r"(b0), "r"(b1));
}

// ---------------- tf32 tensor-core GEMM ----------------
// C[M,N] = act( A[M,K] @ B[K,N] ) (+ X residual)
// A, B must already be tf32-rounded fp32. 256 threads, 8 warps.
// ACT: 0 none, 1 exp(-|x|). CVTOUT: round outputs to tf32.
template<int BM, int BN, int WM, int WN, int ACT, bool RESID, bool CVTOUT>
__global__ void __launch_bounds__(256, 2)
gemm_mma(const float* __restrict__ A, const float* __restrict__ Bm,
         const float* __restrict__ X, float* __restrict__ C,
         int Nd, int Kd)
{
    constexpr int BK = 16, ST = 4;
    constexpr int AST = BK + 4;          // 20 floats (80B rows; 8B-aligned)
    constexpr int BST = BN + 8;          // conflict-free for frag reads
    constexpr int ATILE = BM * AST;
    constexpr int BTILE = BK * BST;
    extern __shared__ float sm[];
    float* sA = sm;
    float* sB = sm + ST * ATILE;

    const int t = threadIdx.x;
    const int w = t >> 5, lane = t & 31, g = lane >> 2, tig = lane & 3;
    constexpr int WNC = BN / WN;
    constexpr int MT = WM / 16, NT = WN / 8;
    const int wm = (w / WNC) * WM, wn = (w % WNC) * WN;

    const long row0 = (long)blockIdx.y * BM;
    const int  col0 = blockIdx.x * BN;

    float acc[MT][NT][4];
    #pragma unroll
    for (int i = 0; i < MT; i++)
        #pragma unroll
        for (int j = 0; j < NT; j++)
            #pragma unroll
            for (int r = 0; r < 4; r++) acc[i][j][r] = 0.f;

    const int KT = Kd / BK;

    auto issue = [&](int kt) {
        int s = kt & (ST - 1);
        int kb = kt * BK;
        // A tile: BM x BK, 8B chunks, natural -> [m][k] layout
        #pragma unroll
        for (int i = 0; i < BM * BK / 512; i++) {
            int idx = t + i * 256;
            int r = idx >> 3, c2 = idx & 7;
            cpa8(&sA[s * ATILE + r * AST + c2 * 2],
                 A + (row0 + r) * Kd + kb + c2 * 2);
        }
        // B tile: BK x BN, 16B chunks, natural [k][n] layout
        #pragma unroll
        for (int i = 0; i < (BK * BN + 1023) / 1024; i++) {
            int idx = t + i * 256;
            if (BK * BN / 4 > 256 || idx < BK * BN / 4) {
                int r = idx / (BN / 4), c4 = idx % (BN / 4);
                cpa16(&sB[s * BTILE + r * BST + c4 * 4],
                      Bm + (long)(kb + r) * Nd + col0 + c4 * 4);
            }
        }
    };

    #pragma unroll
    for (int p = 0; p < ST - 1; p++) { if (p < KT) issue(p); cp_commit(); }

    for (int kt = 0; kt < KT; kt++) {
        cp_wait<ST - 2>();
        __syncthreads();
        int nx = kt + ST - 1;
        if (nx < KT) issue(nx);
        cp_commit();

        const float* As_ = sA + (kt & (ST - 1)) * ATILE;
        const float* Bs_ = sB + (kt & (ST - 1)) * BTILE;
        #pragma unroll
        for (int ks = 0; ks < 2; ks++) {
            unsigned af[MT][4];
            #pragma unroll
            for (int mt = 0; mt < MT; mt++) {
                const float* ab = As_ + (wm + mt * 16 + g) * AST + ks * 8 + tig;
                af[mt][0] = __float_as_uint(ab[0]);
                af[mt][1] = __float_as_uint(ab[8 * AST]);
                af[mt][2] = __float_as_uint(ab[4]);
                af[mt][3] = __float_as_uint(ab[8 * AST + 4]);
            }
            unsigned bf[NT][2];
            #pragma unroll
            for (int nt = 0; nt < NT; nt++) {
                const float* bb = Bs_ + (ks * 8 + tig) * BST + wn + nt * 8 + g;
                bf[nt][0] = __float_as_uint(bb[0]);
                bf[nt][1] = __float_as_uint(bb[4 * BST]);
            }
            #pragma unroll
            for (int mt = 0; mt < MT; mt++)
                #pragma unroll
                for (int nt = 0; nt < NT; nt++)
                    mma_tf32(acc[mt][nt][0], acc[mt][nt][1], acc[mt][nt][2], acc[mt][nt][3],
                             af[mt][0], af[mt][1], af[mt][2], af[mt][3],
                             bf[nt][0], bf[nt][1]);
        }
    }
    cp_wait<0>();

    // epilogue
    #pragma unroll
    for (int mt = 0; mt < MT; mt++) {
        long r0 = row0 + wm + mt * 16 + g;
        long r1 = r0 + 8;
        #pragma unroll
        for (int nt = 0; nt < NT; nt++) {
            int c = col0 + wn + nt * 8 + 2 * tig;
            float v00 = acc[mt][nt][0], v01 = acc[mt][nt][1];
            float v10 = acc[mt][nt][2], v11 = acc[mt][nt][3];
            if (ACT == 1) {
                v00 = expf(-fabsf(v00)); v01 = expf(-fabsf(v01));
                v10 = expf(-fabsf(v10)); v11 = expf(-fabsf(v11));
            }
            if (RESID) {
                float2 x0 = *(const float2*)(X + r0 * Nd + c);
                float2 x1 = *(const float2*)(X + r1 * Nd + c);
                v00 += x0.x; v01 += x0.y; v10 += x1.x; v11 += x1.y;
            }
            if (CVTOUT) {
                v00 = to_tf32(v00); v01 = to_tf32(v01);
                v10 = to_tf32(v10); v11 = to_tf32(v11);
            }
            *(float2*)(C + r0 * Nd + c) = make_float2(v00, v01);
            *(float2*)(C + r1 * Nd + c) = make_float2(v10, v11);
        }
    }
}

// ---------------- weight tf32 rounding ----------------
__global__ void cvtw_k(const float* __restrict__ src, float* __restrict__ dst, int n4) {
    int i = blockIdx.x * blockDim.x + threadIdx.x;
    if (i < n4) {
        float4 v = ((const float4*)src)[i];
        v.x = to_tf32(v.x); v.y = to_tf32(v.y); v.z = to_tf32(v.z); v.w = to_tf32(v.w);
        ((float4*)dst)[i] = v;
    }
}

// ---------------- silu(g)*u, tf32-rounded ----------------
__global__ void silu_k(const float* __restrict__ gg, const float* __restrict__ uu,
                       float* __restrict__ ff) {
    long i = (long)blockIdx.x * blockDim.x + threadIdx.x;
    float4 gv = ((const float4*)gg)[i];
    float4 uv = ((const float4*)uu)[i];
    float4 r;
    r.x = to_tf32(gv.x / (1.f + expf(-gv.x)) * uv.x);
    r.y = to_tf32(gv.y / (1.f + expf(-gv.y)) * uv.y);
    r.z = to_tf32(gv.z / (1.f + expf(-gv.z)) * uv.z);
    r.w = to_tf32(gv.w / (1.f + expf(-gv.w)) * uv.w);
    ((float4*)ff)[i] = r;
}

// ---------------- embedding gather ----------------
__global__ void embed_k(const int* __restrict__ ids, const float* __restrict__ emb,
                        float* __restrict__ x) {
    long n = blockIdx.x;
    int  t = threadIdx.x;  // 128 threads x float4 (D=512)
    ((float4*)x)[n * 128 + t] = ((const float4*)emb)[(long)ids[n] * 128 + t];
}

// ---------------- rmsnorm (output tf32-rounded: feeds GEMMs) ----------------
__global__ void rmsnorm_k(const float* __restrict__ x, const float* __restrict__ g,
                          float* __restrict__ o) {
    long n = blockIdx.x;
    int  t = threadIdx.x;  // 128
    float4 v = ((const float4*)(x + n * Dd))[t];
    float ss = v.x * v.x + v.y * v.y + v.z * v.z + v.w * v.w;
    #pragma unroll
    for (int o2 = 16; o2; o2 >>= 1) ss += __shfl_xor_sync(0xffffffffu, ss, o2);
    __shared__ float smr[4];
    if ((t & 31) == 0) smr[t >> 5] = ss;
    __syncthreads();
    float tot = smr[0] + smr[1] + smr[2] + smr[3];
    float sc = rsqrtf(tot * (1.f / 512.f) + 1e-6f);
    float4 gg = ((const float4*)g)[t];
    float4 r;
    r.x = to_tf32(v.x * sc * gg.x); r.y = to_tf32(v.y * sc * gg.y);
    r.z = to_tf32(v.z * sc * gg.z); r.w = to_tf32(v.w * sc * gg.w);
    ((float4*)(o + n * Dd))[t] = r;
}

// ---------------- zero scratch accumulators ----------------
__global__ void zero_k() {
    int i = blockIdx.x * blockDim.x + threadIdx.x;
    if (i < Bb * HK * Mm * DH) g_kv[i] = 0.f;
    if (i < Bb * HK * Mm)      g_z[i]  = 0.f;
    if (i < Bb * Dd)           g_xm[i] = 0.f;
}

// ---------------- kv state + normalizer ----------------
__global__ __launch_bounds__(256) void kvz_k(const float* __restrict__ pk,
                                             const float* __restrict__ v) {
    int bk = blockIdx.x;
    int b  = bk / HK, hk = bk % HK;
    int s0 = blockIdx.y * 256;
    __shared__ float spk[8][64], sv[8][64];
    int t  = threadIdx.x;
    int mB = (t & 15) * 4, dB = (t >> 4) * 4;
    float acc[4][4] = {};
    float zacc = 0.f;

    for (int st = 0; st < 32; st++) {
        int sbase = s0 + st * 8;
        {
            int half = t >> 7, tt = t & 127;
            int sl = tt >> 4, c = (tt & 15) * 4;
            long row = ((long)(b * Ss + sbase + sl) * HK + hk) * 64;
            const float* src = half ? v : pk;
            float4 val = *(const float4*)(src + row + c);
            float* dst = half ? &sv[sl][c] : &spk[sl][c];
            *(float4*)dst = val;
        }
        __syncthreads();
        #pragma unroll
        for (int ssi = 0; ssi < 8; ssi++) {
            float pm[4], vv[4];
            #pragma unroll
            for (int i = 0; i < 4; i++) { pm[i] = spk[ssi][mB + i]; vv[i] = sv[ssi][dB + i]; }
            #pragma unroll
            for (int i = 0; i < 4; i++)
                #pragma unroll
                for (int j = 0; j < 4; j++) acc[i][j] += pm[i] * vv[j];
            if (t < 64) zacc += spk[ssi][t];
        }
        __syncthreads();
    }
    long base = (long)bk * 64 * 64;
    #pragma unroll
    for (int i = 0; i < 4; i++)
        #pragma unroll
        for (int j = 0; j < 4; j++)
            atomicAdd(&g_kv[base + (mB + i) * 64 + dB + j], acc[i][j]);
    if (t < 64) atomicAdd(&g_z[bk * 64 + t], zacc);
}

// ---------------- attention combine (output tf32: feeds Wo GEMM) ----------------
__global__ __launch_bounds__(256) void attn_k(const float* __restrict__ pq,
                                              float* __restrict__ attn) {
    int bk = blockIdx.x;
    int b  = bk / HK, hk = bk % HK;
    int sTile = blockIdx.y * 64;
    __shared__ float kvs[64][64];
    __shared__ float zs[64];
    int t = threadIdx.x;
    {
        float* kf = &kvs[0][0];
        const float4* src = (const float4*)(g_kv + (long)bk * 4096);
        #pragma unroll
        for (int l = 0; l < 4; l++) ((float4*)kf)[t + l * 256] = src[t + l * 256];
        if (t < 16) ((float4*)zs)[t] = ((const float4*)(g_z + bk * 64))[t];
    }
    __syncthreads();
    int w = t >> 5, lane = t & 31;
    for (int it = 0; it < 32; it++) {
        int pi = w * 32 + it;
        int sl = pi >> 2, gq = pi & 3;
        long n = (long)b * Ss + sTile + sl;
        const float* pqp = pq + (n * Hh + hk * Gg + gq) * 64;
        float a0 = 0.f, a1 = 0.f, den = 0.f;
        #pragma unroll 8
        for (int m = 0; m < 64; m++) {
            float pm = pqp[m];
            a0  += pm * kvs[m][lane];
            a1  += pm * kvs[m][lane + 32];
            den += pm * zs[m];
        }
        float r = 1.f / (den + 1e-6f);
        float* op = attn + n * 512 + (hk * Gg + gq) * 64;
        op[lane]      = to_tf32(a0 * r);
        op[lane + 32] = to_tf32(a1 * r);
    }
}

// ---------------- mean pool ----------------
__global__ void pool_k(const float* __restrict__ x) {
    int b = blockIdx.x, chunk = blockIdx.y;
    int t = threadIdx.x;
    float2 acc = make_float2(0.f, 0.f);
    const float* base = x + ((long)b * Ss + chunk * 256) * Dd + t * 2;
    #pragma unroll 4
    for (int s = 0; s < 256; s++) {
        float2 v = *(const float2*)(base + (long)s * Dd);
        acc.x += v.x; acc.y += v.y;
    }
    atomicAdd(&g_xm[b * Dd + t * 2],     acc.x);
    atomicAdd(&g_xm[b * Dd + t * 2 + 1], acc.y);
}

// ---------------- classifier head ----------------
__global__ void head_k(const float* __restrict__ Wc, const float* __restrict__ bc,
                       float* __restrict__ out) {
    int w = threadIdx.x >> 5, lane = threadIdx.x & 31;
    for (int p = w; p < Bb * NCLS; p += 8) {
        int b = p >> 1, c = p & 1;
        float s = 0.f;
        for (int d = lane; d < Dd; d += 32) s += g_xm[b * Dd + d] * Wc[d * NCLS + c];
        #pragma unroll
        for (int o = 16; o; o >>= 1) s += __shfl_xor_sync(0xffffffffu, s, o);
        if (lane == 0) out[p] = s * (1.f / (float)Ss) + bc[c];
    }
}

// ---------------- launch ----------------
extern "C" void kernel_launch(void* const* d_in, const int* in_sizes, int n_in,
                              void* d_out, int out_size) {
    const int*   ids  = (const int*)  d_in[0];
    const float* emb  = (const float*)d_in[1];
    const float* Wq   = (const float*)d_in[2];
    const float* Wk   = (const float*)d_in[3];
    const float* Wv   = (const float*)d_in[4];
    const float* Wphi = (const float*)d_in[5];
    const float* Wo   = (const float*)d_in[6];
    const float* g1   = (const float*)d_in[7];
    const float* g2   = (const float*)d_in[8];
    const float* Wg   = (const float*)d_in[9];
    const float* Wu   = (const float*)d_in[10];
    const float* Wd   = (const float*)d_in[11];
    const float* Wc   = (const float*)d_in[12];
    const float* bc   = (const float*)d_in[13];
    float* out = (float*)d_out;

    // resolve device-global scratch addresses
    float *x, *h, *q, *k, *v, *pq, *pk, *ff, *u2;
    float *wq, *wk, *wv, *wphi, *wo, *wg, *wu, *wd;
    cudaGetSymbolAddress((void**)&x,  g_x);
    cudaGetSymbolAddress((void**)&h,  g_h);
    cudaGetSymbolAddress((void**)&q,  g_q);
    cudaGetSymbolAddress((void**)&k,  g_k);
    cudaGetSymbolAddress((void**)&v,  g_v);
    cudaGetSymbolAddress((void**)&pq, g_pq);
    cudaGetSymbolAddress((void**)&pk, g_pk);
    cudaGetSymbolAddress((void**)&ff, g_ff);
    cudaGetSymbolAddress((void**)&u2, g_u2);
    cudaGetSymbolAddress((void**)&wq, g_wq);
    cudaGetSymbolAddress((void**)&wk, g_wk);
    cudaGetSymbolAddress((void**)&wv, g_wv);
    cudaGetSymbolAddress((void**)&wphi, g_wphi);
    cudaGetSymbolAddress((void**)&wo, g_wo);
    cudaGetSymbolAddress((void**)&wg, g_wg);
    cudaGetSymbolAddress((void**)&wu, g_wu);
    cudaGetSymbolAddress((void**)&wd, g_wd);
    float* attn = q;  // q dead after phi

    // smem opt-in for the >48KB GEMM configs (idempotent; capture-safe)
    constexpr int SM128 = 4 * (128 * 20 + 16 * 136) * 4;  // 75776 B
    constexpr int SM64  = 4 * (128 * 20 + 16 * 72)  * 4;  // 59392 B
    cudaFuncSetAttribute(gemm_mma<128,128,64,32,0,false,true >, cudaFuncAttributeMaxDynamicSharedMemorySize, SM128);
    cudaFuncSetAttribute(gemm_mma<128,128,64,32,0,false,false>, cudaFuncAttributeMaxDynamicSharedMemorySize, SM128);
    cudaFuncSetAttribute(gemm_mma<128,128,64,32,0,true ,false>, cudaFuncAttributeMaxDynamicSharedMemorySize, SM128);
    cudaFuncSetAttribute(gemm_mma<128, 64,32,32,1,false,false>, cudaFuncAttributeMaxDynamicSharedMemorySize, SM64);

    zero_k<<<256, 256>>>();

    // round weights to tf32 (rna) once per invocation
    auto cvtw = [&](const float* s, float* d, int n) {
        cvtw_k<<<(n / 4 + 255) / 256, 256>>>(s, d, n / 4);
    };
    cvtw(Wq,   wq,   Dd * Hh * DH);
    cvtw(Wk,   wk,   Dd * HK * DH);
    cvtw(Wv,   wv,   Dd * HK * DH);
    cvtw(Wphi, wphi, DH * Mm);
    cvtw(Wo,   wo,   Hh * DH * Dd);
    cvtw(Wg,   wg,   Dd * DFF);
    cvtw(Wu,   wu,   Dd * DFF);
    cvtw(Wd,   wd,   DFF * Dd);

    embed_k  <<<Nn, 128>>>(ids, emb, x);
    rmsnorm_k<<<Nn, 128>>>(x, g1, h);

    // projections (q,k tf32-rounded outputs: they feed the phi GEMMs)
    gemm_mma<128,128,64,32,0,false,true ><<<dim3(Dd / 128, Nn / 128), 256, SM128>>>(h, wq, nullptr, q, Hh * DH, Dd);
    gemm_mma<128,128,64,32,0,false,true ><<<dim3(1,        Nn / 128), 256, SM128>>>(h, wk, nullptr, k, HK * DH, Dd);
    gemm_mma<128,128,64,32,0,false,false><<<dim3(1,        Nn / 128), 256, SM128>>>(h, wv, nullptr, v, HK * DH, Dd);

    // Laplacian feature maps (rows = per-(token,head) contiguous 64-vectors)
    gemm_mma<128, 64,32,32,1,false,false><<<dim3(1, (Nn * Hh) / 128), 256, SM64>>>(q, wphi, nullptr, pq, Mm, DH);
    gemm_mma<128, 64,32,32,1,false,false><<<dim3(1, (Nn * HK) / 128), 256, SM64>>>(k, wphi, nullptr, pk, Mm, DH);

    // global kv state + normalizer, then combine
    kvz_k <<<dim3(Bb * HK, 32),      256>>>(pk, v);
    attn_k<<<dim3(Bb * HK, Ss / 64), 256>>>(pq, attn);

    // output projection + residual
    gemm_mma<128,128,64,32,0,true ,false><<<dim3(Dd / 128, Nn / 128), 256, SM128>>>(attn, wo, x, x, Dd, Dd);

    // FFN
    rmsnorm_k<<<Nn, 128>>>(x, g2, h);
    gemm_mma<128,128,64,32,0,false,false><<<dim3(DFF / 128, Nn / 128), 256, SM128>>>(h, wg, nullptr, ff, DFF, Dd);
    gemm_mma<128,128,64,32,0,false,false><<<dim3(DFF / 128, Nn / 128), 256, SM128>>>(h, wu, nullptr, u2, DFF, Dd);
    silu_k<<<(int)(((long)Nn * DFF / 4) / 256), 256>>>(ff, u2, ff);
    gemm_mma<128,128,64,32,0,true ,false><<<dim3(Dd / 128, Nn / 128), 256, SM128>>>(ff, wd, x, x, Dd, DFF);

    // pool + head
    pool_k<<<dim3(Bb, 32), 256>>>(x);
    head_k<<<1, 256>>>(Wc, bc, out);
}